// round 17
// baseline (speedup 1.0000x reference)
#include <cuda_runtime.h>
#include <math.h>

// Problem constants: B=2, L=128, H=768, C=6, nhops=2
#define NC  6
#define LL  128
#define WS  1600     // WT row stride (1554 padded)

// Scratch (allocation-free: __device__ globals)
__device__ __align__(16) float g_WcT[NC * WS];       // (feat_w@cls_w)^T [c][k], k<1554
__device__ __align__(16) float g_W2T[NC * WS];       // (feat_w@Wc1)^T   [c][k], k<1554
__device__ float g_fbc[NC];                          // feat_b @ cls_w
__device__ float g_fbW2[NC];                         // feat_b @ Wc1
__device__ float g_pqr0[513 * NC], g_pool0[256 * NC];
__device__ float g_pqr1[513 * NC];

// ---- shared dotW body: 512 threads, 16 warps x 2 rows = 32 k-rows per block ----
__device__ __forceinline__ void dotW_body(float* sbuf, int blk2,
                                          const float* __restrict__ feat_w,
                                          const float* __restrict__ feat_b,
                                          const float* __restrict__ cls_w, int which) {
    int tid = threadIdx.x;
    for (int idx = tid; idx < NC * 1536; idx += 512) {
        int c = idx / 1536, k = idx % 1536;
        sbuf[idx] = which ? g_WcT[c * WS + k] : cls_w[k * NC + c];
    }
    __syncthreads();
    int w = tid >> 5, lane = tid & 31;
    const float4* swv = (const float4*)sbuf;
    if (blk2 < 49) {
        int k0 = blk2 * 32 + w * 2;
        bool v0 = (k0 < 1554), v1 = (k0 + 1 < 1554);
        const float4* f0 = (const float4*)(feat_w + (size_t)k0 * 1536);
        const float4* f1 = (const float4*)(feat_w + (size_t)(k0 + 1) * 1536);
        float s[2][NC];
        #pragma unroll
        for (int r = 0; r < 2; r++)
            #pragma unroll
            for (int c = 0; c < NC; c++) s[r][c] = 0.f;
        #pragma unroll 4
        for (int it = 0; it < 12; it++) {
            int col = it * 32 + lane;
            float4 a0 = v0 ? f0[col] : make_float4(0.f, 0.f, 0.f, 0.f);
            float4 a1 = v1 ? f1[col] : make_float4(0.f, 0.f, 0.f, 0.f);
            #pragma unroll
            for (int c = 0; c < NC; c++) {
                float4 wv = swv[c * 384 + col];
                s[0][c] += a0.x * wv.x + a0.y * wv.y + a0.z * wv.z + a0.w * wv.w;
                s[1][c] += a1.x * wv.x + a1.y * wv.y + a1.z * wv.z + a1.w * wv.w;
            }
        }
        #pragma unroll
        for (int r = 0; r < 2; r++)
            #pragma unroll
            for (int c = 0; c < NC; c++) {
                float v = s[r][c];
                #pragma unroll
                for (int o = 16; o; o >>= 1) v += __shfl_down_sync(0xffffffffu, v, o);
                if (lane == 0) {
                    int k = k0 + r;
                    if (k < WS) {
                        float outv = (k < 1554) ? v : 0.f;
                        if (which) g_W2T[c * WS + k] = outv;
                        else       g_WcT[c * WS + k] = outv;
                    }
                }
            }
    } else if (w < NC) {
        const float4* fb = (const float4*)feat_b;
        const float4* cv = swv + w * 384;
        float s = 0.f;
        #pragma unroll 4
        for (int it = 0; it < 12; it++) {
            int col = it * 32 + lane;
            float4 a = fb[col], b = cv[col];
            s += a.x * b.x + a.y * b.y + a.z * b.z + a.w * b.w;
        }
        #pragma unroll
        for (int o = 16; o; o >>= 1) s += __shfl_down_sync(0xffffffffu, s, o);
        if (lane == 0) { if (which) g_fbW2[w] = s; else g_fbc[w] = s; }
    }
}

// ================= kA: pp0 (blocks 0..11) || dotW0 (blocks 12..61) =================
__global__ void __launch_bounds__(512) kA(const float* __restrict__ hidden,
                                          const float* __restrict__ cls_w,
                                          const float* __restrict__ cls_b,
                                          const float* __restrict__ am,
                                          const float* __restrict__ feat_w,
                                          const float* __restrict__ feat_b) {
    __shared__ float sbuf[9216];
    int tid = threadIdx.x;
    if (blockIdx.x >= 12) {
        dotW_body(sbuf, blockIdx.x - 12, feat_w, feat_b, cls_w, 0);
        return;
    }
    int b = blockIdx.x / NC, c = blockIdx.x % NC;
    float* sw  = sbuf;
    float* sp  = sbuf + 1536;
    float* sq  = sbuf + 1664;
    float* smm = sbuf + 1792;
    float* sm1 = sbuf + 1920;
    float* sm2 = sbuf + 2048;
    float* part = sbuf + 2176;
    for (int e = tid; e < 1536; e += 512) sw[e] = cls_w[e * NC + c];
    __syncthreads();
    int k = tid & 127, isq = (tid >> 7) & 1, hh = tid >> 8;
    {
        const float4* hr = (const float4*)(hidden + (size_t)(b * LL + k) * 768);
        const float4* w4 = (const float4*)(sw + isq * 768);
        float s = 0.f;
        #pragma unroll 8
        for (int it = 0; it < 96; it++) {
            int col = hh * 96 + it;
            float4 a = hr[col], x = w4[col];
            s += a.x * x.x + a.y * x.y + a.z * x.z + a.w * x.w;
        }
        part[tid] = s;
    }
    __syncthreads();
    if (tid < 256) {
        float s2 = part[tid] + part[tid + 256];
        if (isq) sq[k] = s2; else { sp[k] = s2; smm[k] = am[b * LL + k]; }
    }
    __syncthreads();
    float r = cls_b[c];
    if (tid < 256) {
        float mk = smm[k], pk = sp[k], qk = sq[k];
        float mx = -INFINITY;
        if (isq == 0) {
            #pragma unroll 4
            for (int i = 0; i < LL; i++) {
                float mv = (i <= k) ? smm[i] * mk : 0.f;
                mx = fmaxf(mx, (sp[i] + qk + r) * mv);
            }
            sm1[k] = mx;
        } else {
            #pragma unroll 4
            for (int i = 0; i < LL; i++) {
                float mv = (i >= k) ? mk * smm[i] : 0.f;
                mx = fmaxf(mx, (pk + sq[i] + r) * mv);
            }
            sm2[k] = mx;
        }
    }
    __syncthreads();
    if (tid < 256 && isq == 0) {
        int rw = b * LL + k;
        g_pool0[rw * NC + c] = fmaxf(sm1[k], sm2[k]);
        g_pqr0[rw * NC + c] = sp[k];
        g_pqr0[(256 + rw) * NC + c] = sq[k];
        if (b == 0 && k == 0) g_pqr0[512 * NC + c] = r;
    }
}

// ================= kB: dotW1 (blocks 0..49) || probs1 (blocks 50..306) =================
__global__ void __launch_bounds__(512) kB(const float* __restrict__ hidden,
                                          const float* __restrict__ cls_w,
                                          const float* __restrict__ cls_b,
                                          const float* __restrict__ feat_w,
                                          const float* __restrict__ feat_b) {
    __shared__ float sbuf[9216];
    if (blockIdx.x < 50) {
        dotW_body(sbuf, blockIdx.x, feat_w, feat_b, cls_w, 1);
        return;
    }
    int w = threadIdx.x >> 5, lane = threadIdx.x & 31;
    if (w >= 12) return;
    int row = (blockIdx.x - 50) * 2 + (w / 6);
    int c = w % 6;
    if (row >= 513) return;
    float s = 0.f;
    if (row < 512) {
        const float4* hr = (const float4*)(hidden + (size_t)(row < 256 ? row : row - 256) * 768);
        const float4* wr = (const float4*)(g_WcT + (size_t)c * WS + (row < 256 ? 0 : 768));
        #pragma unroll
        for (int it = 0; it < 6; it++) {
            int k4 = it * 32 + lane;
            float4 a = hr[k4], b = wr[k4];
            s += a.x * b.x + a.y * b.y + a.z * b.z + a.w * b.w;
        }
    }
    #pragma unroll
    for (int o = 16; o; o >>= 1) s += __shfl_down_sync(0xffffffffu, s, o);
    if (lane == 0) {
        const float* wt = g_WcT + (size_t)c * WS + 1536;
        if (row < 256) {
            #pragma unroll
            for (int t = 0; t < 6; t++) s += g_pool0[row * NC + t] * wt[t];
        } else if (row < 512) {
            #pragma unroll
            for (int t = 0; t < 6; t++) s += g_pool0[(row - 256) * NC + t] * wt[6 + t];
        }
        #pragma unroll
        for (int t = 0; t < 6; t++) s += g_pqr0[row * NC + t] * wt[12 + t];
        if (row == 512) s += g_fbc[c] + cls_b[c];
        g_pqr1[row * NC + c] = s;
    }
}

// ================= kCD: fused probs2 + pool1 + logits =================
// 32 blocks x 512: block = (b, i-octet). Recomputes q2 for all 128 j of batch b,
// pool1 from staged pqr1, p2 for its 8 i rows, r2; writes 8 output rows.
__global__ void __launch_bounds__(512) kCD(const float* __restrict__ hidden,
                                           const float* __restrict__ cls_b,
                                           const float* __restrict__ am,
                                           float* __restrict__ out) {
    __shared__ float4 sW2q[6 * 192];                 // W2T[c][768..1536)
    __shared__ float sp1[768], sq1[768], sr1[8], sam[128];
    __shared__ float spool0[768], spq0p[768], spq0q[768], spool1[768];
    __shared__ float sq2r[768], sp2[48], sr2[8];
    __shared__ float sw2t[120], swct[120];           // tails [c*20+t], t<18

    int tid = threadIdx.x;
    int b = blockIdx.x >> 4, ig = blockIdx.x & 15;
    int i0 = ig * 8;

    // ---- stage ----
    for (int idx = tid; idx < 1152; idx += 512) {
        int c = idx / 192, pos = idx % 192;
        sW2q[c * 192 + pos] = ((const float4*)(g_W2T + (size_t)c * WS + 768))[pos];
    }
    {
        const float4* p1 = (const float4*)(g_pqr1 + (size_t)(b * LL) * NC);
        const float4* q1 = (const float4*)(g_pqr1 + (size_t)(256 + b * LL) * NC);
        const float4* p0 = (const float4*)(g_pqr0 + (size_t)(b * LL) * NC);
        const float4* q0 = (const float4*)(g_pqr0 + (size_t)(256 + b * LL) * NC);
        const float4* pl = (const float4*)(g_pool0 + (size_t)(b * LL) * NC);
        if (tid < 192) {
            ((float4*)sp1)[tid]   = p1[tid];
            ((float4*)sq1)[tid]   = q1[tid];
            ((float4*)spq0p)[tid] = p0[tid];
        } else if (tid < 384) {
            int t = tid - 192;
            ((float4*)spq0q)[t]  = q0[t];
            ((float4*)spool0)[t] = pl[t];
        }
    }
    if (tid < 128) sam[tid] = am[b * LL + tid];
    if (tid >= 128 && tid < 134) sr1[tid - 128] = g_pqr1[512 * NC + (tid - 128)];
    for (int idx = tid; idx < 108; idx += 512) {
        int c = idx / 18, t = idx % 18;
        sw2t[c * 20 + t] = g_W2T[(size_t)c * WS + 1536 + t];
        swct[c * 20 + t] = g_WcT[(size_t)c * WS + 1536 + t];
    }
    __syncthreads();

    // ---- pool1 (exact reference max order) ----
    for (int idx = tid; idx < 768; idx += 512) {
        int k = idx / 6, c = idx % 6;
        float r = sr1[c], mk = sam[k];
        float pk = sp1[k * 6 + c], qk = sq1[k * 6 + c];
        float mx = -INFINITY;
        #pragma unroll 4
        for (int i = 0; i < 128; i++) {
            float mi = sam[i];
            float mv1 = (i <= k) ? mi * mk : 0.f;
            mx = fmaxf(mx, (sp1[i * 6 + c] + qk + r) * mv1);
            float mv2 = (i >= k) ? mk * mi : 0.f;
            mx = fmaxf(mx, (pk + sq1[i * 6 + c] + r) * mv2);
        }
        spool1[idx] = mx;
    }
    __syncthreads();

    int w = tid >> 5, lane = tid & 31;
    // ---- q2 dense dots: warp w -> j in [w*8, w*8+8), 4-row batches ----
    #pragma unroll
    for (int g = 0; g < 2; g++) {
        int jb = w * 8 + g * 4;
        float acc[4][6];
        #pragma unroll
        for (int r = 0; r < 4; r++)
            #pragma unroll
            for (int c = 0; c < 6; c++) acc[r][c] = 0.f;
        const float4* h0 = (const float4*)(hidden + (size_t)(b * LL + jb + 0) * 768);
        const float4* h1 = (const float4*)(hidden + (size_t)(b * LL + jb + 1) * 768);
        const float4* h2 = (const float4*)(hidden + (size_t)(b * LL + jb + 2) * 768);
        const float4* h3 = (const float4*)(hidden + (size_t)(b * LL + jb + 3) * 768);
        #pragma unroll
        for (int u = 0; u < 6; u++) {
            int pos = u * 32 + lane;
            float4 v0 = h0[pos], v1 = h1[pos], v2 = h2[pos], v3 = h3[pos];
            #pragma unroll
            for (int c = 0; c < 6; c++) {
                float4 wv = sW2q[c * 192 + pos];
                acc[0][c] += v0.x * wv.x + v0.y * wv.y + v0.z * wv.z + v0.w * wv.w;
                acc[1][c] += v1.x * wv.x + v1.y * wv.y + v1.z * wv.z + v1.w * wv.w;
                acc[2][c] += v2.x * wv.x + v2.y * wv.y + v2.z * wv.z + v2.w * wv.w;
                acc[3][c] += v3.x * wv.x + v3.y * wv.y + v3.z * wv.z + v3.w * wv.w;
            }
        }
        #pragma unroll
        for (int r = 0; r < 4; r++)
            #pragma unroll
            for (int c = 0; c < 6; c++) {
                float v = acc[r][c];
                #pragma unroll
                for (int o = 16; o; o >>= 1) v += __shfl_down_sync(0xffffffffu, v, o);
                if (lane == 0) sq2r[(jb + r) * 6 + c] = v;
            }
    }
    // ---- p2 dense dots: pi = w, w+16, w+32 ----
    for (int pi = w; pi < 48; pi += 16) {
        int il = i0 + pi / 6, c = pi % 6;
        const float4* hr = (const float4*)(hidden + (size_t)(b * LL + il) * 768);
        const float4* wr = (const float4*)(g_W2T + (size_t)c * WS);
        float s = 0.f;
        #pragma unroll
        for (int u = 0; u < 6; u++) {
            int pos = u * 32 + lane;
            float4 a = hr[pos], wv = wr[pos];
            s += a.x * wv.x + a.y * wv.y + a.z * wv.z + a.w * wv.w;
        }
        #pragma unroll
        for (int o = 16; o; o >>= 1) s += __shfl_down_sync(0xffffffffu, s, o);
        if (lane == 0) sp2[pi] = s;
    }
    // ---- r2 ----
    if (tid < 6) {
        int c = tid;
        float s = g_fbW2[c] + g_fbc[c] + cls_b[c];
        #pragma unroll
        for (int t = 0; t < 6; t++)
            s += g_pqr0[512 * NC + t] * sw2t[c * 20 + 12 + t]
               + sr1[t] * swct[c * 20 + 12 + t];
        sr2[c] = s;
    }
    __syncthreads();

    // ---- corrections ----
    for (int idx = tid; idx < 768; idx += 512) {
        int j = idx / 6, c = idx % 6;
        float s = sq2r[idx];
        #pragma unroll
        for (int t = 0; t < 6; t++)
            s += spool0[j * 6 + t] * sw2t[c * 20 + 6 + t]
               + spool1[j * 6 + t] * swct[c * 20 + 6 + t]
               + spq0q[j * 6 + t] * sw2t[c * 20 + 12 + t]
               + sq1[j * 6 + t] * swct[c * 20 + 12 + t];
        sq2r[idx] = s + sr2[c];
    }
    if (tid < 48) {
        int il = i0 + tid / 6, c = tid % 6;
        float s = sp2[tid];
        #pragma unroll
        for (int t = 0; t < 6; t++)
            s += spool0[il * 6 + t] * sw2t[c * 20 + t]
               + spool1[il * 6 + t] * swct[c * 20 + t]
               + spq0p[il * 6 + t] * sw2t[c * 20 + 12 + t]
               + sp1[il * 6 + t] * swct[c * 20 + 12 + t];
        sp2[tid] = s;
    }
    __syncthreads();

    // ---- store 8 output rows, coalesced float4 ----
    for (int idx = tid; idx < 1536; idx += 512) {
        int row = idx / 192, e4 = idx % 192;
        int e = e4 * 4;
        float4 o;
        o.x = sq2r[e]     + sp2[row * 6 + (e    ) % 6];
        o.y = sq2r[e + 1] + sp2[row * 6 + (e + 1) % 6];
        o.z = sq2r[e + 2] + sp2[row * 6 + (e + 2) % 6];
        o.w = sq2r[e + 3] + sp2[row * 6 + (e + 3) % 6];
        *(float4*)(out + (size_t)(b * LL + i0 + row) * 768 + e) = o;
    }
}

extern "C" void kernel_launch(void* const* d_in, const int* in_sizes, int n_in,
                              void* d_out, int out_size) {
    const float* hidden = (const float*)d_in[0];
    const float* am     = (const float*)d_in[1];
    const float* cls_w  = (const float*)d_in[2];
    const float* cls_b  = (const float*)d_in[3];
    const float* feat_w = (const float*)d_in[4];
    const float* feat_b = (const float*)d_in[5];

    kA<<<62, 512>>>(hidden, cls_w, cls_b, am, feat_w, feat_b);   // pp0 || Wc
    kB<<<307, 512>>>(hidden, cls_w, cls_b, feat_w, feat_b);      // W2 || probs1
    kCD<<<32, 512>>>(hidden, cls_b, am, (float*)d_out);          // probs2+pool1+logits
}